// round 9
// baseline (speedup 1.0000x reference)
#include <cuda_runtime.h>

// NCDE decoder: B=4096, 255 RK4 steps, C=16, H=128, O=4.
// Kernel 1: one 128-thread block per TWO batch elements (thread = h for both).
//   Packed tanh-arg weights live in SMEM (shared by both chains); quad-
//   reciprocal tanh (1 rcp / 4 tanh); fma.rn.f32x2 packed args; z streamed
//   to a __device__ scratch.
// Kernel 2: memory-bound projection out = z_all @ W_out + b_out.

#define Hh 128
#define Cc 16
#define NSTEP 255
#define L2E2 2.8853900817779268f   // 2*log2(e), folded into W2/b2

typedef unsigned long long ull;

__device__ float zscr[4096 * 256 * 128];   // 512 MB z trajectory scratch

__device__ __forceinline__ ull pack2(float lo, float hi) {
    ull r; asm("mov.b64 %0, {%1, %2};" : "=l"(r) : "f"(lo), "f"(hi)); return r;
}
__device__ __forceinline__ void unpack2(ull v, float& lo, float& hi) {
    asm("mov.b64 {%0, %1}, %2;" : "=f"(lo), "=f"(hi) : "l"(v));
}
__device__ __forceinline__ ull fma2(ull a, ull b, ull c) {
    ull d; asm("fma.rn.f32x2 %0, %1, %2, %3;" : "=l"(d) : "l"(a), "l"(b), "l"(c)); return d;
}
__device__ __forceinline__ float ex2f(float x) {
    float e; asm("ex2.approx.f32 %0, %1;" : "=f"(e) : "f"(x)); return e;
}
__device__ __forceinline__ float rcpf(float x) {
    float r; asm("rcp.approx.f32 %0, %1;" : "=f"(r) : "f"(x)); return r;
}
// volatile: pin weight loads inside each stage so ptxas cannot CSE-hoist
// 768B of weights into registers (would spill).
__device__ __forceinline__ void lds_w2(unsigned addr, ull& a, ull& b) {
    asm volatile("ld.shared.v2.u64 {%0, %1}, [%2];" : "=l"(a), "=l"(b) : "r"(addr));
}

__device__ __forceinline__ void redsum2(float& a, float& b) {
#pragma unroll
    for (int off = 16; off; off >>= 1) {
        a += __shfl_xor_sync(0xffffffffu, a, off);
        b += __shfl_xor_sync(0xffffffffu, b, off);
    }
}
__device__ __forceinline__ void redsum4(float& a, float& b, float& c, float& d) {
#pragma unroll
    for (int off = 16; off; off >>= 1) {
        a += __shfl_xor_sync(0xffffffffu, a, off);
        b += __shfl_xor_sync(0xffffffffu, b, off);
        c += __shfl_xor_sync(0xffffffffu, c, off);
        d += __shfl_xor_sync(0xffffffffu, d, off);
    }
}

__global__ __launch_bounds__(128, 5) void ncde_kernel(
    const float* __restrict__ coeffs,   // (B, 255, 64)
    const float* __restrict__ W_init,   // (16, 128)
    const float* __restrict__ b_init,   // (128)
    const float* __restrict__ W1,       // (128, 2)
    const float* __restrict__ b1,       // (2)
    const float* __restrict__ W2,       // (2, 2048)
    const float* __restrict__ b2)       // (2048)
{
    const int h    = threadIdx.x;
    const int lane = h & 31;
    const int warp = h >> 5;

    // weights: [qi][h] -> ull2 (16B), conflict-free across lanes (banks 4h%32)
    __shared__ __align__(16) ull wa_s[4][Hh][2];
    __shared__ __align__(16) ull wb_s[4][Hh][2];
    __shared__ __align__(16) ull bb_s[4][Hh][2];
    __shared__ __align__(16) float sxd2[2][3][Cc];  // per-batch -2*xdot tables
    __shared__ float ssum[2][3];
    __shared__ __align__(16) float sred[2][16];     // [phase][warp*4 + j]
    __shared__ float sa0[2][Cc];

    // ---- pack weights into smem (arg scale 2*log2e pre-folded) ----
#pragma unroll
    for (int p = 0; p < 8; p++) {
        wa_s[p >> 1][h][p & 1] = pack2(W2[h * Cc + 2 * p] * L2E2,
                                       W2[h * Cc + 2 * p + 1] * L2E2);
        wb_s[p >> 1][h][p & 1] = pack2(W2[Hh * Cc + h * Cc + 2 * p] * L2E2,
                                       W2[Hh * Cc + h * Cc + 2 * p + 1] * L2E2);
        bb_s[p >> 1][h][p & 1] = pack2(b2[h * Cc + 2 * p] * L2E2,
                                       b2[h * Cc + 2 * p + 1] * L2E2);
    }
    const unsigned wa_a = (unsigned)__cvta_generic_to_shared(&wa_s[0][h][0]);
    const unsigned wb_a = (unsigned)__cvta_generic_to_shared(&wb_s[0][h][0]);
    const unsigned bb_a = (unsigned)__cvta_generic_to_shared(&bb_s[0][h][0]);

    const float w1a = W1[h * 2 + 0], w1b = W1[h * 2 + 1];
    const float b10 = b1[0], b11 = b1[1];

    const float* crowA = coeffs + (size_t)(blockIdx.x * 2 + 0) * (NSTEP * 64);
    const float* crowB = coeffs + (size_t)(blockIdx.x * 2 + 1) * (NSTEP * 64);
    float* zrowA = zscr + (size_t)(blockIdx.x * 2 + 0) * (256 * Hh) + h;
    float* zrowB = zscr + (size_t)(blockIdx.x * 2 + 1) * (256 * Hh) + h;

    float pbA = 0.f, pcA = 0.f, pdA = 0.f, pbB = 0.f, pcB = 0.f, pdB = 0.f;
    if (h < Cc) {
        sa0[0][h] = crowA[h]; sa0[1][h] = crowB[h];
        pbA = crowA[16 + h]; pcA = crowA[32 + h]; pdA = crowA[48 + h];
        pbB = crowB[16 + h]; pcB = crowB[32 + h]; pdB = crowB[48 + h];
    }

    // SW1 = column sums of W1 (k = S + q decomposition)
    {
        float r0 = w1a, r1 = w1b;
        redsum2(r0, r1);
        if (lane == 0) { sred[0][warp * 4] = r0; sred[0][warp * 4 + 1] = r1; }
    }
    __syncthreads();   // also publishes smem weights + sa0
    float SW1a, SW1b;
    {
        const float4 f0 = *(const float4*)&sred[0][0];
        const float4 f1 = *(const float4*)&sred[0][4];
        const float4 f2 = *(const float4*)&sred[0][8];
        const float4 f3 = *(const float4*)&sred[0][12];
        SW1a = f0.x + f1.x + f2.x + f3.x;
        SW1b = f0.y + f1.y + f2.y + f3.y;
    }

    // z0 = X0 @ W_init + b_init for both batches
    float zA = b_init[h], zB = zA;
#pragma unroll
    for (int c = 0; c < Cc; c++) {
        const float wi = W_init[c * Hh + h];
        zA = fmaf(sa0[0][c], wi, zA);
        zB = fmaf(sa0[1][c], wi, zB);
    }
    zrowA[0] = zA;
    zrowB[0] = zB;

    // uz for both batches
    float uzA0, uzA1, uzB0, uzB1;
    {
        float r0 = zA * w1a, r1 = zA * w1b, r2 = zB * w1a, r3 = zB * w1b;
        redsum4(r0, r1, r2, r3);
        if (lane == 0) {
            sred[1][warp * 4 + 0] = r0; sred[1][warp * 4 + 1] = r1;
            sred[1][warp * 4 + 2] = r2; sred[1][warp * 4 + 3] = r3;
        }
        __syncthreads();
        const float4 f0 = *(const float4*)&sred[1][0];
        const float4 f1 = *(const float4*)&sred[1][4];
        const float4 f2 = *(const float4*)&sred[1][8];
        const float4 f3 = *(const float4*)&sred[1][12];
        uzA0 = f0.x + f1.x + f2.x + f3.x;
        uzA1 = f0.y + f1.y + f2.y + f3.y;
        uzB0 = f0.z + f1.z + f2.z + f3.z;
        uzB1 = f0.w + f1.w + f2.w + f3.w;
    }

    int ph = 0;
    for (int t = 0; t < NSTEP; t++) {
        if (h < Cc) {
            sxd2[0][0][h] = -2.f * pbA;
            sxd2[0][1][h] = -2.f * fmaf(0.25f, pdA, fmaf(0.5f, pcA, pbA));
            sxd2[0][2][h] = -2.f * (pbA + pcA + pdA);
            sxd2[1][0][h] = -2.f * pbB;
            sxd2[1][1][h] = -2.f * fmaf(0.25f, pdB, fmaf(0.5f, pcB, pbB));
            sxd2[1][2][h] = -2.f * (pbB + pcB + pdB);
        }
        if (warp == 0) {   // lanes >= 16 hold zeros
            float v[6] = { pbA, pcA, pdA, pbB, pcB, pdB };
#pragma unroll
            for (int off = 1; off < 16; off <<= 1)
#pragma unroll
                for (int i = 0; i < 6; i++)
                    v[i] += __shfl_xor_sync(0xffffffffu, v[i], off);
            if (lane == 0) {
                ssum[0][0] = v[0];
                ssum[0][1] = fmaf(0.25f, v[2], fmaf(0.5f, v[1], v[0]));
                ssum[0][2] = v[0] + v[1] + v[2];
                ssum[1][0] = v[3];
                ssum[1][1] = fmaf(0.25f, v[5], fmaf(0.5f, v[4], v[3]));
                ssum[1][2] = v[3] + v[4] + v[5];
            }
        }
        __syncthreads();
        if (h < Cc && (t + 1) < NSTEP) {
            const float* rA = crowA + (size_t)(t + 1) * 64;
            const float* rB = crowB + (size_t)(t + 1) * 64;
            pbA = rA[16 + h]; pcA = rA[32 + h]; pdA = rA[48 + h];
            pbB = rB[16 + h]; pcB = rB[32 + h]; pdB = rB[48 + h];
        }
        const float SA0 = ssum[0][0], SAh = ssum[0][1], SA1 = ssum[0][2];
        const float SB0 = ssum[1][0], SBh = ssum[1][1], SB1 = ssum[1][2];

        float ukA0 = 0.f, ukA1 = 0.f, sA0 = 0.f, sA1 = 0.f, ksumA = 0.f;
        float ukB0 = 0.f, ukB1 = 0.f, sB0 = 0.f, sB1 = 0.f, ksumB = 0.f;

#pragma unroll
        for (int st = 0; st < 4; st++) {
            const float alpha = (st == 0) ? 0.f : (st == 3) ? 1.f : 0.5f;
            const int   xi    = (st == 0) ? 0   : (st == 3) ? 2   : 1;
            const float wgt   = (st == 0 || st == 3) ? 1.f : 2.f;
            const float SstA  = (st == 0) ? SA0 : (st == 3) ? SA1 : SAh;
            const float SstB  = (st == 0) ? SB0 : (st == 3) ? SB1 : SBh;

            const float hA0 = fmaxf(fmaf(alpha, ukA0, uzA0) + b10, 0.f);
            const float hA1 = fmaxf(fmaf(alpha, ukA1, uzA1) + b11, 0.f);
            const float hB0 = fmaxf(fmaf(alpha, ukB0, uzB0) + b10, 0.f);
            const float hB1 = fmaxf(fmaf(alpha, ukB1, uzB1) + b11, 0.f);
            const ull HA0 = pack2(hA0, hA0), HA1 = pack2(hA1, hA1);
            const ull HB0 = pack2(hB0, hB0), HB1 = pack2(hB1, hB1);

            float qA = 0.f, qB = 0.f;
#pragma unroll
            for (int qi = 0; qi < 4; qi++) {
                ull w0, w1, v0, v1, c0, c1;
                lds_w2(wa_a + qi * (Hh * 16), w0, w1);
                lds_w2(wb_a + qi * (Hh * 16), v0, v1);
                lds_w2(bb_a + qi * (Hh * 16), c0, c1);

                const ull yA0 = fma2(HA0, w0, fma2(HA1, v0, c0));
                const ull yA1 = fma2(HA0, w1, fma2(HA1, v1, c1));
                const ull yB0 = fma2(HB0, w0, fma2(HB1, v0, c0));
                const ull yB1 = fma2(HB0, w1, fma2(HB1, v1, c1));
                float a0, a1, a2, a3, e0, e1, e2, e3;
                unpack2(yA0, a0, a1); unpack2(yA1, a2, a3);
                unpack2(yB0, e0, e1); unpack2(yB1, e2, e3);
                const float tA0 = ex2f(fminf(a0, 30.f)) + 1.f;
                const float tA1 = ex2f(fminf(a1, 30.f)) + 1.f;
                const float tA2 = ex2f(fminf(a2, 30.f)) + 1.f;
                const float tA3 = ex2f(fminf(a3, 30.f)) + 1.f;
                const float tB0 = ex2f(fminf(e0, 30.f)) + 1.f;
                const float tB1 = ex2f(fminf(e1, 30.f)) + 1.f;
                const float tB2 = ex2f(fminf(e2, 30.f)) + 1.f;
                const float tB3 = ex2f(fminf(e3, 30.f)) + 1.f;
                const float4 xA = *(const float4*)&sxd2[0][xi][4 * qi];
                const float4 xB = *(const float4*)&sxd2[1][xi][4 * qi];
                const float PA0 = tA0 * tA1, PA1 = tA2 * tA3;
                const float NA0 = fmaf(xA.y, tA0, xA.x * tA1);
                const float NA1 = fmaf(xA.w, tA2, xA.z * tA3);
                const float PB0 = tB0 * tB1, PB1 = tB2 * tB3;
                const float NB0 = fmaf(xB.y, tB0, xB.x * tB1);
                const float NB1 = fmaf(xB.w, tB2, xB.z * tB3);
                const float RA = rcpf(PA0 * PA1);
                const float RB = rcpf(PB0 * PB1);
                qA = fmaf(RA, fmaf(NA1, PA0, NA0 * PA1), qA);
                qB = fmaf(RB, fmaf(NB1, PB0, NB0 * PB1), qB);
            }

            float r0 = qA * w1a, r1 = qA * w1b, r2 = qB * w1a, r3 = qB * w1b;
            redsum4(r0, r1, r2, r3);
            if (lane == 0) {
                sred[ph][warp * 4 + 0] = r0; sred[ph][warp * 4 + 1] = r1;
                sred[ph][warp * 4 + 2] = r2; sred[ph][warp * 4 + 3] = r3;
            }
            __syncthreads();
            const float4 f0 = *(const float4*)&sred[ph][0];
            const float4 f1 = *(const float4*)&sred[ph][4];
            const float4 f2 = *(const float4*)&sred[ph][8];
            const float4 f3 = *(const float4*)&sred[ph][12];
            const float QA0 = f0.x + f1.x + f2.x + f3.x;
            const float QA1 = f0.y + f1.y + f2.y + f3.y;
            const float QB0 = f0.z + f1.z + f2.z + f3.z;
            const float QB1 = f0.w + f1.w + f2.w + f3.w;
            ukA0 = fmaf(SstA, SW1a, QA0);  ukA1 = fmaf(SstA, SW1b, QA1);
            ukB0 = fmaf(SstB, SW1a, QB0);  ukB1 = fmaf(SstB, SW1b, QB1);
            sA0 = fmaf(wgt, ukA0, sA0);    sA1 = fmaf(wgt, ukA1, sA1);
            sB0 = fmaf(wgt, ukB0, sB0);    sB1 = fmaf(wgt, ukB1, sB1);
            ksumA = fmaf(wgt, SstA + qA, ksumA);
            ksumB = fmaf(wgt, SstB + qB, ksumB);
            ph ^= 1;
        }

        zA   = fmaf(ksumA, 1.f / 6.f, zA);
        uzA0 = fmaf(sA0,   1.f / 6.f, uzA0);
        uzA1 = fmaf(sA1,   1.f / 6.f, uzA1);
        zB   = fmaf(ksumB, 1.f / 6.f, zB);
        uzB0 = fmaf(sB0,   1.f / 6.f, uzB0);
        uzB1 = fmaf(sB1,   1.f / 6.f, uzB1);

        zrowA[(size_t)(t + 1) * Hh] = zA;
        zrowB[(size_t)(t + 1) * Hh] = zB;
    }
}

// out[b,t,:] = z[b,t,:] @ W_out + b_out.  One warp per (b,t) row.
__global__ __launch_bounds__(256) void proj_kernel(
    const float* __restrict__ W_out,    // (128, 4)
    const float* __restrict__ b_out,    // (4)
    float* __restrict__ out)            // (B*256, 4)
{
    const int row  = (blockIdx.x * 256 + threadIdx.x) >> 5;   // b*256 + t
    const int lane = threadIdx.x & 31;

    const float4 z4 = *(const float4*)&zscr[(size_t)row * Hh + lane * 4];
    const float4 w0 = *(const float4*)&W_out[(lane * 4 + 0) * 4];
    const float4 w1 = *(const float4*)&W_out[(lane * 4 + 1) * 4];
    const float4 w2 = *(const float4*)&W_out[(lane * 4 + 2) * 4];
    const float4 w3 = *(const float4*)&W_out[(lane * 4 + 3) * 4];

    float p0 = fmaf(z4.x, w0.x, fmaf(z4.y, w1.x, fmaf(z4.z, w2.x, z4.w * w3.x)));
    float p1 = fmaf(z4.x, w0.y, fmaf(z4.y, w1.y, fmaf(z4.z, w2.y, z4.w * w3.y)));
    float p2 = fmaf(z4.x, w0.z, fmaf(z4.y, w1.z, fmaf(z4.z, w2.z, z4.w * w3.z)));
    float p3 = fmaf(z4.x, w0.w, fmaf(z4.y, w1.w, fmaf(z4.z, w2.w, z4.w * w3.w)));
    redsum4(p0, p1, p2, p3);

    if (lane < 4) {
        const float v = (lane == 0) ? p0 : (lane == 1) ? p1 : (lane == 2) ? p2 : p3;
        out[(size_t)row * 4 + lane] = v + b_out[lane];
    }
}

extern "C" void kernel_launch(void* const* d_in, const int* in_sizes, int n_in,
                              void* d_out, int out_size) {
    const float* coeffs = (const float*)d_in[0];
    const float* W_init = (const float*)d_in[1];
    const float* b_init = (const float*)d_in[2];
    const float* W1     = (const float*)d_in[3];
    const float* b1     = (const float*)d_in[4];
    const float* W2     = (const float*)d_in[5];
    const float* b2     = (const float*)d_in[6];
    const float* W_out  = (const float*)d_in[7];
    const float* b_out  = (const float*)d_in[8];
    float* out = (float*)d_out;

    ncde_kernel<<<2048, 128>>>(coeffs, W_init, b_init, W1, b1, W2, b2);
    proj_kernel<<<(4096 * 256) / 8, 256>>>(W_out, b_out, out);
}

// round 10
// speedup vs baseline: 1.2245x; 1.2245x over previous
#include <cuda_runtime.h>

// NCDE decoder: B=4096, 255 RK4 steps, C=16, H=128, O=4.
// Kernel 1 (scan): one 128-thread block per batch element (thread = h).
//   Quad-reciprocal tanh (1 rcp / 4 tanh), fma.rn.f32x2 packed args,
//   double-buffered xdot tables (next step's tables written under stage-3's
//   barrier -> 4 barriers/step). z streamed to __device__ scratch.
// Kernel 2 (proj): shfl-free smem-tiled out = z_all @ W_out + b_out.

#define Hh 128
#define Cc 16
#define NSTEP 255
#define L2E2 2.8853900817779268f   // 2*log2(e), folded into W2/b2

typedef unsigned long long ull;

__device__ float zscr[4096 * 256 * 128];   // 512 MB z trajectory scratch

__device__ __forceinline__ ull pack2(float lo, float hi) {
    ull r; asm("mov.b64 %0, {%1, %2};" : "=l"(r) : "f"(lo), "f"(hi)); return r;
}
__device__ __forceinline__ void unpack2(ull v, float& lo, float& hi) {
    asm("mov.b64 {%0, %1}, %2;" : "=f"(lo), "=f"(hi) : "l"(v));
}
__device__ __forceinline__ ull fma2(ull a, ull b, ull c) {
    ull d; asm("fma.rn.f32x2 %0, %1, %2, %3;" : "=l"(d) : "l"(a), "l"(b), "l"(c)); return d;
}
__device__ __forceinline__ float ex2f(float x) {
    float e; asm("ex2.approx.f32 %0, %1;" : "=f"(e) : "f"(x)); return e;
}
__device__ __forceinline__ float rcpf(float x) {
    float r; asm("rcp.approx.f32 %0, %1;" : "=f"(r) : "f"(x)); return r;
}

__device__ __forceinline__ void redsum2(float& a, float& b) {
#pragma unroll
    for (int off = 16; off; off >>= 1) {
        a += __shfl_xor_sync(0xffffffffu, a, off);
        b += __shfl_xor_sync(0xffffffffu, b, off);
    }
}

__global__ __launch_bounds__(128, 6) void ncde_kernel(
    const float* __restrict__ coeffs,   // (B, 255, 64)
    const float* __restrict__ W_init,   // (16, 128)
    const float* __restrict__ b_init,   // (128)
    const float* __restrict__ W1,       // (128, 2)
    const float* __restrict__ b1,       // (2)
    const float* __restrict__ W2,       // (2, 2048)
    const float* __restrict__ b2)       // (2048)
{
    const int b    = blockIdx.x;
    const int h    = threadIdx.x;
    const int lane = h & 31;
    const int warp = h >> 5;

    __shared__ __align__(16) float sxd2[2][3][Cc];  // double-buffered -2*xdot
    __shared__ float ssum[2][3];                    // double-buffered channel sums
    __shared__ __align__(16) float sred[2][8];      // double-buffered uk reduction
    __shared__ float sa0[Cc];

    // ---- per-thread packed weight slices (arg scale 2*log2e pre-folded) ----
    ull wa[8], wbp[8], b2p[8];
#pragma unroll
    for (int p = 0; p < 8; p++) {
        wa[p]  = pack2(W2[h * Cc + 2 * p] * L2E2,           W2[h * Cc + 2 * p + 1] * L2E2);
        wbp[p] = pack2(W2[Hh * Cc + h * Cc + 2 * p] * L2E2, W2[Hh * Cc + h * Cc + 2 * p + 1] * L2E2);
        b2p[p] = pack2(b2[h * Cc + 2 * p] * L2E2,           b2[h * Cc + 2 * p + 1] * L2E2);
    }
    const float w1a = W1[h * 2 + 0], w1b = W1[h * 2 + 1];
    const float b10 = b1[0], b11 = b1[1];

    const float* crow = coeffs + (size_t)b * (NSTEP * 64);
    float* zrow = zscr + (size_t)b * (256 * Hh) + h;

    float pb = 0.f, pc = 0.f, pd = 0.f;
    if (h < Cc) { sa0[h] = crow[h]; pb = crow[16 + h]; pc = crow[32 + h]; pd = crow[48 + h]; }

    // SW1 = column sums of W1 (for k = S + q decomposition)
    {
        float r0 = w1a, r1 = w1b;
        redsum2(r0, r1);
        if (lane == 0) { sred[0][warp * 2] = r0; sred[0][warp * 2 + 1] = r1; }
    }
    __syncthreads();
    float SW1a, SW1b;
    {
        const float4 fa = *(const float4*)&sred[0][0];
        const float4 fb = *(const float4*)&sred[0][4];
        SW1a = fa.x + fa.z + fb.x + fb.z;
        SW1b = fa.y + fa.w + fb.y + fb.w;
    }

    // z0 = X0 @ W_init + b_init
    float z = b_init[h];
#pragma unroll
    for (int c = 0; c < Cc; c++) z = fmaf(sa0[c], W_init[c * Hh + h], z);
    zrow[0] = z;

    // ---- step-0 xdot tables into buffer 0 (published by the uz barrier) ----
    if (h < Cc) {
        sxd2[0][0][h] = -2.f * pb;
        sxd2[0][1][h] = -2.f * fmaf(0.25f, pd, fmaf(0.5f, pc, pb));
        sxd2[0][2][h] = -2.f * (pb + pc + pd);
    }
    if (warp == 0) {   // lanes >= 16 hold zeros
        float SB = pb, SC = pc, SD = pd;
#pragma unroll
        for (int off = 1; off < 16; off <<= 1) {
            SB += __shfl_xor_sync(0xffffffffu, SB, off);
            SC += __shfl_xor_sync(0xffffffffu, SC, off);
            SD += __shfl_xor_sync(0xffffffffu, SD, off);
        }
        if (lane == 0) {
            ssum[0][0] = SB;
            ssum[0][1] = fmaf(0.25f, SD, fmaf(0.5f, SC, SB));
            ssum[0][2] = SB + SC + SD;
        }
    }

    // uz = z @ W1 ; prefetch step-1 coeffs
    float uz0, uz1;
    {
        float r0 = z * w1a, r1 = z * w1b;
        redsum2(r0, r1);
        if (lane == 0) { sred[1][warp * 2] = r0; sred[1][warp * 2 + 1] = r1; }
        if (h < Cc) { pb = crow[64 + 16 + h]; pc = crow[64 + 32 + h]; pd = crow[64 + 48 + h]; }
        __syncthreads();
        const float4 fa = *(const float4*)&sred[1][0];
        const float4 fb = *(const float4*)&sred[1][4];
        uz0 = fa.x + fa.z + fb.x + fb.z;
        uz1 = fa.y + fa.w + fb.y + fb.w;
    }

    int ph = 0;
    for (int t = 0; t < NSTEP; t++) {
        const int buf  = t & 1;
        const int nbuf = buf ^ 1;
        const float S0 = ssum[buf][0], Sh_ = ssum[buf][1], S1 = ssum[buf][2];

        float uk0 = 0.f, uk1 = 0.f, s0 = 0.f, s1 = 0.f, ksum = 0.f;

#pragma unroll
        for (int st = 0; st < 4; st++) {
            const float alpha = (st == 0) ? 0.f : (st == 3) ? 1.f : 0.5f;
            const int   xi    = (st == 0) ? 0   : (st == 3) ? 2   : 1;
            const float wgt   = (st == 0 || st == 3) ? 1.f : 2.f;
            const float Sst   = (st == 0) ? S0 : (st == 3) ? S1 : Sh_;

            const float h0 = fmaxf(fmaf(alpha, uk0, uz0) + b10, 0.f);
            const float h1 = fmaxf(fmaf(alpha, uk1, uz1) + b11, 0.f);
            const ull H0 = pack2(h0, h0), H1 = pack2(h1, h1);

            float qa = 0.f, qb = 0.f;
#pragma unroll
            for (int qi = 0; qi < 4; qi++) {
                ull y0 = fma2(H0, wa[2 * qi],     fma2(H1, wbp[2 * qi],     b2p[2 * qi]));
                ull y1 = fma2(H0, wa[2 * qi + 1], fma2(H1, wbp[2 * qi + 1], b2p[2 * qi + 1]));
                float ya, yb, yc, yd;
                unpack2(y0, ya, yb); unpack2(y1, yc, yd);
                const float t0 = ex2f(fminf(ya, 30.f)) + 1.f;
                const float t1 = ex2f(fminf(yb, 30.f)) + 1.f;
                const float t2 = ex2f(fminf(yc, 30.f)) + 1.f;
                const float t3 = ex2f(fminf(yd, 30.f)) + 1.f;
                const float4 x4 = *(const float4*)&sxd2[buf][xi][4 * qi];
                const float P0 = t0 * t1;
                const float N0 = fmaf(x4.y, t0, x4.x * t1);
                const float P1 = t2 * t3;
                const float N1 = fmaf(x4.w, t2, x4.z * t3);
                const float R  = rcpf(P0 * P1);
                const float N  = fmaf(N1, P0, N0 * P1);
                if (qi & 1) qb = fmaf(R, N, qb); else qa = fmaf(R, N, qa);
            }
            const float q = qa + qb;            // k_h = Sst + q_h

            if (st == 3) {
                // next step's tables into the other buffer, published by the
                // stage-3 barrier below (pb holds coeffs for step t+1).
                if (h < Cc) {
                    sxd2[nbuf][0][h] = -2.f * pb;
                    sxd2[nbuf][1][h] = -2.f * fmaf(0.25f, pd, fmaf(0.5f, pc, pb));
                    sxd2[nbuf][2][h] = -2.f * (pb + pc + pd);
                }
                if (warp == 0) {
                    float SB = pb, SC = pc, SD = pd;
#pragma unroll
                    for (int off = 1; off < 16; off <<= 1) {
                        SB += __shfl_xor_sync(0xffffffffu, SB, off);
                        SC += __shfl_xor_sync(0xffffffffu, SC, off);
                        SD += __shfl_xor_sync(0xffffffffu, SD, off);
                    }
                    if (lane == 0) {
                        ssum[nbuf][0] = SB;
                        ssum[nbuf][1] = fmaf(0.25f, SD, fmaf(0.5f, SC, SB));
                        ssum[nbuf][2] = SB + SC + SD;
                    }
                }
            }

            float r0 = q * w1a, r1 = q * w1b;
            redsum2(r0, r1);
            if (lane == 0) { sred[ph][warp * 2] = r0; sred[ph][warp * 2 + 1] = r1; }
            if (st == 3 && h < Cc && t + 2 < NSTEP) {   // prefetch coeffs t+2
                const float* r2 = crow + (size_t)(t + 2) * 64;
                pb = r2[16 + h]; pc = r2[32 + h]; pd = r2[48 + h];
            }
            __syncthreads();
            const float4 fa = *(const float4*)&sred[ph][0];
            const float4 fb = *(const float4*)&sred[ph][4];
            const float Q0 = fa.x + fa.z + fb.x + fb.z;
            const float Q1 = fa.y + fa.w + fb.y + fb.w;
            uk0 = fmaf(Sst, SW1a, Q0);
            uk1 = fmaf(Sst, SW1b, Q1);
            s0 = fmaf(wgt, uk0, s0);
            s1 = fmaf(wgt, uk1, s1);
            ksum = fmaf(wgt, Sst + q, ksum);
            ph ^= 1;
        }

        z   = fmaf(ksum, 1.f / 6.f, z);
        uz0 = fmaf(s0,   1.f / 6.f, uz0);
        uz1 = fmaf(s1,   1.f / 6.f, uz1);

        zrow[(size_t)(t + 1) * Hh] = z;
    }
}

// out[row,:] = z[row,:] @ W_out + b_out, row = b*256+t.
// 128-thread block tiles 32 rows; thread = (row, o); no shuffles.
__global__ __launch_bounds__(128) void proj_kernel(
    const float* __restrict__ W_out,    // (128, 4)
    const float* __restrict__ b_out,    // (4)
    float* __restrict__ out)            // (B*256, 4)
{
    __shared__ __align__(16) float zs[32][132];   // pitch 132: conflict-free
    __shared__ __align__(16) float wT[4][132];
    __shared__ float bo[4];

    const int t = threadIdx.x;
    const size_t base = (size_t)blockIdx.x * 32;

    // W_out transposed: wT[o][c]
#pragma unroll
    for (int j = 0; j < 4; j++) wT[j][t] = W_out[t * 4 + j];
    if (t < 4) bo[t] = b_out[t];

    // 32 rows x 128 floats = 1024 float4, 8 per thread, coalesced
    const float4* zg = (const float4*)(zscr + base * Hh);
#pragma unroll
    for (int k = 0; k < 8; k++) {
        const int f4  = t + k * 128;
        const int row = f4 >> 5;
        const int c4  = f4 & 31;
        *(float4*)&zs[row][c4 * 4] = zg[f4];
    }
    __syncthreads();

    const int row = t >> 2, o = t & 3;
    float acc[4] = {0.f, 0.f, 0.f, 0.f};
#pragma unroll
    for (int i = 0; i < 8; i++) {
#pragma unroll
        for (int j = 0; j < 4; j++) {
            const float4 zv = *(const float4*)&zs[row][(i * 4 + j) * 4];
            const float4 wv = *(const float4*)&wT[o][(i * 4 + j) * 4];
            acc[j] = fmaf(zv.x, wv.x, acc[j]);
            acc[j] = fmaf(zv.y, wv.y, acc[j]);
            acc[j] = fmaf(zv.z, wv.z, acc[j]);
            acc[j] = fmaf(zv.w, wv.w, acc[j]);
        }
    }
    out[base * 4 + t] = (acc[0] + acc[1]) + (acc[2] + acc[3]) + bo[o];
}

extern "C" void kernel_launch(void* const* d_in, const int* in_sizes, int n_in,
                              void* d_out, int out_size) {
    const float* coeffs = (const float*)d_in[0];
    const float* W_init = (const float*)d_in[1];
    const float* b_init = (const float*)d_in[2];
    const float* W1     = (const float*)d_in[3];
    const float* b1     = (const float*)d_in[4];
    const float* W2     = (const float*)d_in[5];
    const float* b2     = (const float*)d_in[6];
    const float* W_out  = (const float*)d_in[7];
    const float* b_out  = (const float*)d_in[8];
    float* out = (float*)d_out;

    ncde_kernel<<<4096, 128>>>(coeffs, W_init, b_init, W1, b1, W2, b2);
    proj_kernel<<<(4096 * 256) / 32, 128>>>(W_out, b_out, out);
}

// round 12
// speedup vs baseline: 1.3400x; 1.0943x over previous
#include <cuda_runtime.h>

// NCDE decoder: B=4096, 255 RK4 steps, C=16, H=128, O=4.
// Kernel 1 (scan): one 128-thread block per TWO batch elements (thread = h;
//   weights shared between both chains, 48 regs). The two chains' quad loops
//   run serially within each stage (register-lean); their stage reductions
//   merge into ONE redsum4 + ONE barrier -> 2.5 barriers per batch-step.
//   Quad-reciprocal tanh (1 rcp / 4 tanh), fma.rn.f32x2 packed args.
//   z streamed to __device__ scratch; separate memory-bound projection.
// Kernel 2 (proj): shfl-free smem-tiled out = z_all @ W_out + b_out.

#define Hh 128
#define Cc 16
#define NSTEP 255
#define L2E2 2.8853900817779268f   // 2*log2(e), folded into W2/b2

typedef unsigned long long ull;

__device__ float zscr[4096 * 256 * 128];   // 512 MB z trajectory scratch

__device__ __forceinline__ ull pack2(float lo, float hi) {
    ull r; asm("mov.b64 %0, {%1, %2};" : "=l"(r) : "f"(lo), "f"(hi)); return r;
}
__device__ __forceinline__ void unpack2(ull v, float& lo, float& hi) {
    asm("mov.b64 {%0, %1}, %2;" : "=f"(lo), "=f"(hi) : "l"(v));
}
__device__ __forceinline__ ull fma2(ull a, ull b, ull c) {
    ull d; asm("fma.rn.f32x2 %0, %1, %2, %3;" : "=l"(d) : "l"(a), "l"(b), "l"(c)); return d;
}
__device__ __forceinline__ float ex2f(float x) {
    float e; asm("ex2.approx.f32 %0, %1;" : "=f"(e) : "f"(x)); return e;
}
__device__ __forceinline__ float rcpf(float x) {
    float r; asm("rcp.approx.f32 %0, %1;" : "=f"(r) : "f"(x)); return r;
}

__device__ __forceinline__ void redsum2(float& a, float& b) {
#pragma unroll
    for (int off = 16; off; off >>= 1) {
        a += __shfl_xor_sync(0xffffffffu, a, off);
        b += __shfl_xor_sync(0xffffffffu, b, off);
    }
}
__device__ __forceinline__ void redsum4(float& a, float& b, float& c, float& d) {
#pragma unroll
    for (int off = 16; off; off >>= 1) {
        a += __shfl_xor_sync(0xffffffffu, a, off);
        b += __shfl_xor_sync(0xffffffffu, b, off);
        c += __shfl_xor_sync(0xffffffffu, c, off);
        d += __shfl_xor_sync(0xffffffffu, d, off);
    }
}

// One stage's vf partial for one batch: q_h = sum_c tanh(args)*xdot_c
// (xdot pre-scaled by -2; k_h = Sst + q_h). Serial per chain: low reg pressure.
__device__ __forceinline__ float stage_q(
    const ull H0, const ull H1,
    const ull* __restrict__ wa, const ull* __restrict__ wbp,
    const ull* __restrict__ b2p, const float* __restrict__ xd)
{
    float qa = 0.f, qb = 0.f;
#pragma unroll
    for (int qi = 0; qi < 4; qi++) {
        ull y0 = fma2(H0, wa[2 * qi],     fma2(H1, wbp[2 * qi],     b2p[2 * qi]));
        ull y1 = fma2(H0, wa[2 * qi + 1], fma2(H1, wbp[2 * qi + 1], b2p[2 * qi + 1]));
        float ya, yb, yc, yd;
        unpack2(y0, ya, yb); unpack2(y1, yc, yd);
        const float t0 = ex2f(fminf(ya, 30.f)) + 1.f;
        const float t1 = ex2f(fminf(yb, 30.f)) + 1.f;
        const float t2 = ex2f(fminf(yc, 30.f)) + 1.f;
        const float t3 = ex2f(fminf(yd, 30.f)) + 1.f;
        const float4 x4 = *(const float4*)&xd[4 * qi];
        const float P0 = t0 * t1;
        const float N0 = fmaf(x4.y, t0, x4.x * t1);
        const float P1 = t2 * t3;
        const float N1 = fmaf(x4.w, t2, x4.z * t3);
        const float R  = rcpf(P0 * P1);
        const float N  = fmaf(N1, P0, N0 * P1);
        if (qi & 1) qb = fmaf(R, N, qb); else qa = fmaf(R, N, qa);
    }
    return qa + qb;
}

__global__ __launch_bounds__(128, 4) void ncde_kernel(
    const float* __restrict__ coeffs,   // (B, 255, 64)
    const float* __restrict__ W_init,   // (16, 128)
    const float* __restrict__ b_init,   // (128)
    const float* __restrict__ W1,       // (128, 2)
    const float* __restrict__ b1,       // (2)
    const float* __restrict__ W2,       // (2, 2048)
    const float* __restrict__ b2)       // (2048)
{
    const int h    = threadIdx.x;
    const int lane = h & 31;
    const int warp = h >> 5;

    __shared__ __align__(16) float sxd2[2][3][Cc];  // [batch][stage-class][c]
    __shared__ float ssum[2][3];
    __shared__ __align__(16) float sred[2][16];     // [phase][warp*4 + j]
    __shared__ float sa0[2][Cc];

    // ---- per-thread packed weight slices, shared by both chains (48 regs) ----
    ull wa[8], wbp[8], b2p[8];
#pragma unroll
    for (int p = 0; p < 8; p++) {
        wa[p]  = pack2(W2[h * Cc + 2 * p] * L2E2,           W2[h * Cc + 2 * p + 1] * L2E2);
        wbp[p] = pack2(W2[Hh * Cc + h * Cc + 2 * p] * L2E2, W2[Hh * Cc + h * Cc + 2 * p + 1] * L2E2);
        b2p[p] = pack2(b2[h * Cc + 2 * p] * L2E2,           b2[h * Cc + 2 * p + 1] * L2E2);
    }
    const float w1a = W1[h * 2 + 0], w1b = W1[h * 2 + 1];
    const float b10 = b1[0], b11 = b1[1];

    const float* crowA = coeffs + (size_t)(blockIdx.x * 2 + 0) * (NSTEP * 64);
    const float* crowB = coeffs + (size_t)(blockIdx.x * 2 + 1) * (NSTEP * 64);
    float* zrowA = zscr + (size_t)(blockIdx.x * 2 + 0) * (256 * Hh) + h;
    float* zrowB = zscr + (size_t)(blockIdx.x * 2 + 1) * (256 * Hh) + h;

    float pbA = 0.f, pcA = 0.f, pdA = 0.f, pbB = 0.f, pcB = 0.f, pdB = 0.f;
    if (h < Cc) {
        sa0[0][h] = crowA[h]; sa0[1][h] = crowB[h];
        pbA = crowA[16 + h]; pcA = crowA[32 + h]; pdA = crowA[48 + h];
        pbB = crowB[16 + h]; pcB = crowB[32 + h]; pdB = crowB[48 + h];
    }

    // SW1 = column sums of W1 (k = S + q decomposition)
    {
        float r0 = w1a, r1 = w1b;
        redsum2(r0, r1);
        if (lane == 0) { sred[0][warp * 4] = r0; sred[0][warp * 4 + 1] = r1; }
    }
    __syncthreads();
    const float SW1a = sred[0][0] + sred[0][4] + sred[0][8]  + sred[0][12];
    const float SW1b = sred[0][1] + sred[0][5] + sred[0][9]  + sred[0][13];

    // z0 = X0 @ W_init + b_init, both batches
    float zA = b_init[h], zB = zA;
#pragma unroll
    for (int c = 0; c < Cc; c++) {
        const float wi = W_init[c * Hh + h];
        zA = fmaf(sa0[0][c], wi, zA);
        zB = fmaf(sa0[1][c], wi, zB);
    }
    zrowA[0] = zA;
    zrowB[0] = zB;

    // uz for both batches
    float uzA0, uzA1, uzB0, uzB1;
    {
        float r0 = zA * w1a, r1 = zA * w1b, r2 = zB * w1a, r3 = zB * w1b;
        redsum4(r0, r1, r2, r3);
        if (lane == 0) {
            sred[1][warp * 4 + 0] = r0; sred[1][warp * 4 + 1] = r1;
            sred[1][warp * 4 + 2] = r2; sred[1][warp * 4 + 3] = r3;
        }
        __syncthreads();
        const float4 f0 = *(const float4*)&sred[1][0];
        const float4 f1 = *(const float4*)&sred[1][4];
        const float4 f2 = *(const float4*)&sred[1][8];
        const float4 f3 = *(const float4*)&sred[1][12];
        uzA0 = f0.x + f1.x + f2.x + f3.x;
        uzA1 = f0.y + f1.y + f2.y + f3.y;
        uzB0 = f0.z + f1.z + f2.z + f3.z;
        uzB1 = f0.w + f1.w + f2.w + f3.w;
    }

    int ph = 0;
    for (int t = 0; t < NSTEP; t++) {
        // xdot tables for both batches (single-buffered; last reader of the
        // previous step finished before stage-3's barrier)
        if (h < Cc) {
            sxd2[0][0][h] = -2.f * pbA;
            sxd2[0][1][h] = -2.f * fmaf(0.25f, pdA, fmaf(0.5f, pcA, pbA));
            sxd2[0][2][h] = -2.f * (pbA + pcA + pdA);
            sxd2[1][0][h] = -2.f * pbB;
            sxd2[1][1][h] = -2.f * fmaf(0.25f, pdB, fmaf(0.5f, pcB, pbB));
            sxd2[1][2][h] = -2.f * (pbB + pcB + pdB);
        }
        if (warp == 0) {   // lanes >= 16 hold zeros
            float v0 = pbA, v1 = pcA, v2 = pdA, v3 = pbB, v4 = pcB, v5 = pdB;
#pragma unroll
            for (int off = 1; off < 16; off <<= 1) {
                v0 += __shfl_xor_sync(0xffffffffu, v0, off);
                v1 += __shfl_xor_sync(0xffffffffu, v1, off);
                v2 += __shfl_xor_sync(0xffffffffu, v2, off);
                v3 += __shfl_xor_sync(0xffffffffu, v3, off);
                v4 += __shfl_xor_sync(0xffffffffu, v4, off);
                v5 += __shfl_xor_sync(0xffffffffu, v5, off);
            }
            if (lane == 0) {
                ssum[0][0] = v0;
                ssum[0][1] = fmaf(0.25f, v2, fmaf(0.5f, v1, v0));
                ssum[0][2] = v0 + v1 + v2;
                ssum[1][0] = v3;
                ssum[1][1] = fmaf(0.25f, v5, fmaf(0.5f, v4, v3));
                ssum[1][2] = v3 + v4 + v5;
            }
        }
        __syncthreads();
        if (h < Cc && (t + 1) < NSTEP) {       // prefetch next step's coeffs
            const float* rA = crowA + (size_t)(t + 1) * 64;
            const float* rB = crowB + (size_t)(t + 1) * 64;
            pbA = rA[16 + h]; pcA = rA[32 + h]; pdA = rA[48 + h];
            pbB = rB[16 + h]; pcB = rB[32 + h]; pdB = rB[48 + h];
        }
        const float SA0 = ssum[0][0], SAh = ssum[0][1], SA1 = ssum[0][2];
        const float SB0 = ssum[1][0], SBh = ssum[1][1], SB1 = ssum[1][2];

        float ukA0 = 0.f, ukA1 = 0.f, sA0 = 0.f, sA1 = 0.f, ksumA = 0.f;
        float ukB0 = 0.f, ukB1 = 0.f, sB0 = 0.f, sB1 = 0.f, ksumB = 0.f;

#pragma unroll
        for (int st = 0; st < 4; st++) {
            const float alpha = (st == 0) ? 0.f : (st == 3) ? 1.f : 0.5f;
            const int   xi    = (st == 0) ? 0   : (st == 3) ? 2   : 1;
            const float wgt   = (st == 0 || st == 3) ? 1.f : 2.f;
            const float SstA  = (st == 0) ? SA0 : (st == 3) ? SA1 : SAh;
            const float SstB  = (st == 0) ? SB0 : (st == 3) ? SB1 : SBh;

            // chain A quad loop (serial), then chain B (keeps temps 1x)
            const float hA0 = fmaxf(fmaf(alpha, ukA0, uzA0) + b10, 0.f);
            const float hA1 = fmaxf(fmaf(alpha, ukA1, uzA1) + b11, 0.f);
            const float qA = stage_q(pack2(hA0, hA0), pack2(hA1, hA1),
                                     wa, wbp, b2p, &sxd2[0][xi][0]);

            const float hB0 = fmaxf(fmaf(alpha, ukB0, uzB0) + b10, 0.f);
            const float hB1 = fmaxf(fmaf(alpha, ukB1, uzB1) + b11, 0.f);
            const float qB = stage_q(pack2(hB0, hB0), pack2(hB1, hB1),
                                     wa, wbp, b2p, &sxd2[1][xi][0]);

            // merged reduction: one barrier serves both batch chains
            float r0 = qA * w1a, r1 = qA * w1b, r2 = qB * w1a, r3 = qB * w1b;
            redsum4(r0, r1, r2, r3);
            if (lane == 0) {
                sred[ph][warp * 4 + 0] = r0; sred[ph][warp * 4 + 1] = r1;
                sred[ph][warp * 4 + 2] = r2; sred[ph][warp * 4 + 3] = r3;
            }
            __syncthreads();
            const float4 f0 = *(const float4*)&sred[ph][0];
            const float4 f1 = *(const float4*)&sred[ph][4];
            const float4 f2 = *(const float4*)&sred[ph][8];
            const float4 f3 = *(const float4*)&sred[ph][12];
            const float QA0 = f0.x + f1.x + f2.x + f3.x;
            const float QA1 = f0.y + f1.y + f2.y + f3.y;
            const float QB0 = f0.z + f1.z + f2.z + f3.z;
            const float QB1 = f0.w + f1.w + f2.w + f3.w;
            ukA0 = fmaf(SstA, SW1a, QA0);  ukA1 = fmaf(SstA, SW1b, QA1);
            ukB0 = fmaf(SstB, SW1a, QB0);  ukB1 = fmaf(SstB, SW1b, QB1);
            sA0 = fmaf(wgt, ukA0, sA0);    sA1 = fmaf(wgt, ukA1, sA1);
            sB0 = fmaf(wgt, ukB0, sB0);    sB1 = fmaf(wgt, ukB1, sB1);
            ksumA = fmaf(wgt, SstA + qA, ksumA);
            ksumB = fmaf(wgt, SstB + qB, ksumB);
            ph ^= 1;
        }

        zA   = fmaf(ksumA, 1.f / 6.f, zA);
        uzA0 = fmaf(sA0,   1.f / 6.f, uzA0);
        uzA1 = fmaf(sA1,   1.f / 6.f, uzA1);
        zB   = fmaf(ksumB, 1.f / 6.f, zB);
        uzB0 = fmaf(sB0,   1.f / 6.f, uzB0);
        uzB1 = fmaf(sB1,   1.f / 6.f, uzB1);

        zrowA[(size_t)(t + 1) * Hh] = zA;
        zrowB[(size_t)(t + 1) * Hh] = zB;
    }
}

// out[row,:] = z[row,:] @ W_out + b_out, row = b*256+t.
// 128-thread block tiles 32 rows; thread = (row, o); no shuffles.
__global__ __launch_bounds__(128) void proj_kernel(
    const float* __restrict__ W_out,    // (128, 4)
    const float* __restrict__ b_out,    // (4)
    float* __restrict__ out)            // (B*256, 4)
{
    __shared__ __align__(16) float zs[32][132];   // pitch 132: conflict-free
    __shared__ __align__(16) float wT[4][132];
    __shared__ float bo[4];

    const int t = threadIdx.x;
    const size_t base = (size_t)blockIdx.x * 32;

#pragma unroll
    for (int j = 0; j < 4; j++) wT[j][t] = W_out[t * 4 + j];
    if (t < 4) bo[t] = b_out[t];

    const float4* zg = (const float4*)(zscr + base * Hh);
#pragma unroll
    for (int k = 0; k < 8; k++) {
        const int f4  = t + k * 128;
        const int row = f4 >> 5;
        const int c4  = f4 & 31;
        *(float4*)&zs[row][c4 * 4] = zg[f4];
    }
    __syncthreads();

    const int row = t >> 2, o = t & 3;
    float acc[4] = {0.f, 0.f, 0.f, 0.f};
#pragma unroll
    for (int i = 0; i < 8; i++) {
#pragma unroll
        for (int j = 0; j < 4; j++) {
            const float4 zv = *(const float4*)&zs[row][(i * 4 + j) * 4];
            const float4 wv = *(const float4*)&wT[o][(i * 4 + j) * 4];
            acc[j] = fmaf(zv.x, wv.x, acc[j]);
            acc[j] = fmaf(zv.y, wv.y, acc[j]);
            acc[j] = fmaf(zv.z, wv.z, acc[j]);
            acc[j] = fmaf(zv.w, wv.w, acc[j]);
        }
    }
    out[base * 4 + t] = (acc[0] + acc[1]) + (acc[2] + acc[3]) + bo[o];
}

extern "C" void kernel_launch(void* const* d_in, const int* in_sizes, int n_in,
                              void* d_out, int out_size) {
    const float* coeffs = (const float*)d_in[0];
    const float* W_init = (const float*)d_in[1];
    const float* b_init = (const float*)d_in[2];
    const float* W1     = (const float*)d_in[3];
    const float* b1     = (const float*)d_in[4];
    const float* W2     = (const float*)d_in[5];
    const float* b2     = (const float*)d_in[6];
    const float* W_out  = (const float*)d_in[7];
    const float* b_out  = (const float*)d_in[8];
    float* out = (float*)d_out;

    ncde_kernel<<<2048, 128>>>(coeffs, W_init, b_init, W1, b1, W2, b2);
    proj_kernel<<<(4096 * 256) / 32, 128>>>(W_out, b_out, out);
}